// round 1
// baseline (speedup 1.0000x reference)
#include <cuda_runtime.h>
#include <cuda_bf16.h>
#include <math.h>

// Problem constants (fixed by the reference)
#define NNODES 10000
#define NEDGES 320000
#define DIN    512
#define DHID   2048
#define NCLS   40

// ---------------------------------------------------------------------------
// Device scratch (static globals: no runtime allocation allowed)
// ---------------------------------------------------------------------------
__device__ int   g_cnt[NNODES];            // in-degree histogram
__device__ int   g_rowptr[NNODES + 1];     // CSR row pointers (by dst)
__device__ int   g_cursor[NNODES];         // fill cursors
__device__ float g_dinv[NNODES];           // rsqrt(deg+1)
__device__ int   g_csr_src[NEDGES];        // CSR: source node per edge
__device__ float g_csr_coef[NEDGES];       // CSR: dinv[src]*dinv[dst]
__device__ float g_aggX[(size_t)NNODES * DIN];   // propagated x   (20.5 MB)
__device__ float g_h[(size_t)NNODES * DHID];     // hidden layer   (81.9 MB)
__device__ float g_t[(size_t)NNODES * NCLS];     // h @ W2          (1.6 MB)

// ---------------------------------------------------------------------------
// CSR construction
// ---------------------------------------------------------------------------
__global__ void zero_cnt_kernel() {
    for (int i = blockIdx.x * blockDim.x + threadIdx.x; i < NNODES;
         i += gridDim.x * blockDim.x)
        g_cnt[i] = 0;
}

__global__ void count_kernel(const int* __restrict__ dst) {
    int e = blockIdx.x * blockDim.x + threadIdx.x;
    if (e < NEDGES) atomicAdd(&g_cnt[dst[e]], 1);
}

// Single-block exclusive scan over NNODES counters (10 tiles of 1024).
__global__ void scan_kernel() {
    __shared__ int sh[1024];
    __shared__ int carry;
    int tid = threadIdx.x;
    if (tid == 0) { carry = 0; g_rowptr[0] = 0; }
    __syncthreads();
    for (int base = 0; base < NNODES; base += 1024) {
        int i = base + tid;
        int v = (i < NNODES) ? g_cnt[i] : 0;
        sh[tid] = v;
        __syncthreads();
        #pragma unroll
        for (int off = 1; off < 1024; off <<= 1) {
            int t = (tid >= off) ? sh[tid - off] : 0;
            __syncthreads();
            sh[tid] += t;
            __syncthreads();
        }
        int incl = sh[tid];
        if (i < NNODES) g_rowptr[i + 1] = carry + incl;
        __syncthreads();
        if (tid == 1023) carry += sh[1023];
        __syncthreads();
    }
}

__global__ void dinv_cursor_kernel() {
    for (int i = blockIdx.x * blockDim.x + threadIdx.x; i < NNODES;
         i += gridDim.x * blockDim.x) {
        g_dinv[i]   = rsqrtf((float)g_cnt[i] + 1.0f);
        g_cursor[i] = g_rowptr[i];
    }
}

__global__ void fill_kernel(const int* __restrict__ src, const int* __restrict__ dst) {
    int e = blockIdx.x * blockDim.x + threadIdx.x;
    if (e >= NEDGES) return;
    int s = src[e], d = dst[e];
    int p = atomicAdd(&g_cursor[d], 1);
    g_csr_src[p]  = s;
    g_csr_coef[p] = g_dinv[s] * g_dinv[d];
}

// ---------------------------------------------------------------------------
// Layer-1 propagate: aggX[i] = sum_{j->i} coef*x[j] + dinv[i]^2 * x[i]
// One 128-thread block per node; each thread owns one float4 of the 512 feats.
// ---------------------------------------------------------------------------
__global__ void gather1_kernel(const float* __restrict__ x) {
    int i = blockIdx.x;
    int f4 = threadIdx.x;                 // 0..127
    float di = g_dinv[i];
    float self = di * di;
    const float4* xi = (const float4*)&x[(size_t)i * DIN];
    float4 xv = xi[f4];
    float4 acc;
    acc.x = self * xv.x; acc.y = self * xv.y;
    acc.z = self * xv.z; acc.w = self * xv.w;
    int beg = g_rowptr[i], end = g_rowptr[i + 1];
    for (int j = beg; j < end; j++) {
        int s = g_csr_src[j];
        float c = g_csr_coef[j];
        float4 v = ((const float4*)&x[(size_t)s * DIN])[f4];
        acc.x += c * v.x; acc.y += c * v.y;
        acc.z += c * v.z; acc.w += c * v.w;
    }
    ((float4*)&g_aggX[(size_t)i * DIN])[f4] = acc;
}

// ---------------------------------------------------------------------------
// SGEMM1: g_h = relu(g_aggX[10000x512] @ W1[512x2048] + b1)
// 128x128 block tile, BK=8, 256 threads, 8x8 microtile.
// ---------------------------------------------------------------------------
__global__ __launch_bounds__(256, 2)
void sgemm1_kernel(const float* __restrict__ B /*W1*/, const float* __restrict__ bias) {
    __shared__ float As[8][132];   // padded, transposed A tile
    __shared__ float Bs[8][128];
    const float* A = g_aggX;
    float*       C = g_h;

    int block_m = blockIdx.y * 128;
    int block_n = blockIdx.x * 128;
    int tid = threadIdx.x;

    int a_row = tid >> 1;            // 0..127
    int a_col = (tid & 1) << 2;      // 0 or 4
    int b_row = tid >> 5;            // 0..7
    int b_col = (tid & 31) << 2;     // 0..124
    int ty = tid >> 4, tx = tid & 15;

    float acc[8][8];
    #pragma unroll
    for (int i = 0; i < 8; i++)
        #pragma unroll
        for (int j = 0; j < 8; j++) acc[i][j] = 0.0f;

    for (int k0 = 0; k0 < DIN; k0 += 8) {
        float4 av = make_float4(0.f, 0.f, 0.f, 0.f);
        int gm = block_m + a_row;
        if (gm < NNODES) av = *(const float4*)&A[(size_t)gm * DIN + k0 + a_col];
        As[a_col + 0][a_row] = av.x;
        As[a_col + 1][a_row] = av.y;
        As[a_col + 2][a_row] = av.z;
        As[a_col + 3][a_row] = av.w;
        *(float4*)&Bs[b_row][b_col] =
            *(const float4*)&B[(size_t)(k0 + b_row) * DHID + block_n + b_col];
        __syncthreads();
        #pragma unroll
        for (int k = 0; k < 8; k++) {
            float4 a0 = *(const float4*)&As[k][ty * 8];
            float4 a1 = *(const float4*)&As[k][ty * 8 + 4];
            float4 b0 = *(const float4*)&Bs[k][tx * 8];
            float4 b1 = *(const float4*)&Bs[k][tx * 8 + 4];
            float a[8] = {a0.x, a0.y, a0.z, a0.w, a1.x, a1.y, a1.z, a1.w};
            float b[8] = {b0.x, b0.y, b0.z, b0.w, b1.x, b1.y, b1.z, b1.w};
            #pragma unroll
            for (int i = 0; i < 8; i++)
                #pragma unroll
                for (int j = 0; j < 8; j++) acc[i][j] += a[i] * b[j];
        }
        __syncthreads();
    }

    #pragma unroll
    for (int i = 0; i < 8; i++) {
        int gm = block_m + ty * 8 + i;
        if (gm >= NNODES) continue;
        #pragma unroll
        for (int j = 0; j < 8; j += 4) {
            int gn = block_n + tx * 8 + j;
            float4 v;
            v.x = fmaxf(acc[i][j + 0] + bias[gn + 0], 0.f);
            v.y = fmaxf(acc[i][j + 1] + bias[gn + 1], 0.f);
            v.z = fmaxf(acc[i][j + 2] + bias[gn + 2], 0.f);
            v.w = fmaxf(acc[i][j + 3] + bias[gn + 3], 0.f);
            *(float4*)&C[(size_t)gm * DHID + gn] = v;
        }
    }
}

// ---------------------------------------------------------------------------
// SGEMM2: g_t = g_h[10000x2048] @ W2[2048x40]   (no bias here)
// BM=64, BN=40, BK=32, 256 threads, 2x5 microtile.
// ---------------------------------------------------------------------------
__global__ __launch_bounds__(256)
void sgemm2_kernel(const float* __restrict__ B /*W2*/) {
    __shared__ float As[32][65];   // padded, transposed
    __shared__ float Bs[32][40];
    const float* A = g_h;
    float*       C = g_t;

    int block_m = blockIdx.x * 64;
    int tid = threadIdx.x;
    int tr = tid >> 3;   // 0..31
    int tc = tid & 7;    // 0..7

    float acc[2][5];
    #pragma unroll
    for (int i = 0; i < 2; i++)
        #pragma unroll
        for (int j = 0; j < 5; j++) acc[i][j] = 0.0f;

    for (int k0 = 0; k0 < DHID; k0 += 32) {
        // load A tile 64x32 (2 float4 per thread)
        #pragma unroll
        for (int r = 0; r < 2; r++) {
            int q = tid + 256 * r;        // 0..511 float4 slots
            int row = q >> 3;             // 0..63
            int col = (q & 7) << 2;       // 0..28
            float4 av = make_float4(0.f, 0.f, 0.f, 0.f);
            int gm = block_m + row;
            if (gm < NNODES) av = *(const float4*)&A[(size_t)gm * DHID + k0 + col];
            As[col + 0][row] = av.x;
            As[col + 1][row] = av.y;
            As[col + 2][row] = av.z;
            As[col + 3][row] = av.w;
        }
        // load B tile 32x40 (5 scalars per thread)
        #pragma unroll
        for (int r = 0; r < 5; r++) {
            int q = tid + 256 * r;        // 0..1279
            int row = q / 40;
            int col = q % 40;
            Bs[row][col] = B[(size_t)(k0 + row) * NCLS + col];
        }
        __syncthreads();
        #pragma unroll
        for (int k = 0; k < 32; k++) {
            float a0 = As[k][tr * 2 + 0];
            float a1 = As[k][tr * 2 + 1];
            float b[5];
            #pragma unroll
            for (int j = 0; j < 5; j++) b[j] = Bs[k][tc * 5 + j];
            #pragma unroll
            for (int j = 0; j < 5; j++) {
                acc[0][j] += a0 * b[j];
                acc[1][j] += a1 * b[j];
            }
        }
        __syncthreads();
    }

    #pragma unroll
    for (int i = 0; i < 2; i++) {
        int gm = block_m + tr * 2 + i;
        if (gm >= NNODES) continue;
        #pragma unroll
        for (int j = 0; j < 5; j++)
            C[(size_t)gm * NCLS + tc * 5 + j] = acc[i][j];
    }
}

// ---------------------------------------------------------------------------
// Layer-2 propagate + bias: out[i] = sum coef*t[j] + dinv^2*t[i] + b2
// One warp per node; lane handles class c=lane and (if lane<8) c=lane+32.
// ---------------------------------------------------------------------------
__global__ void gather2_kernel(const float* __restrict__ b2, float* __restrict__ out) {
    int gw = (blockIdx.x * blockDim.x + threadIdx.x) >> 5;
    int lane = threadIdx.x & 31;
    if (gw >= NNODES) return;
    int i = gw;
    float di = g_dinv[i];
    float self = di * di;
    int c1 = lane + 32;
    float acc0 = 0.f, acc1 = 0.f;
    int beg = g_rowptr[i], end = g_rowptr[i + 1];
    for (int j = beg; j < end; j++) {
        int s = g_csr_src[j];
        float c = g_csr_coef[j];
        acc0 += c * g_t[(size_t)s * NCLS + lane];
        if (lane < 8) acc1 += c * g_t[(size_t)s * NCLS + c1];
    }
    out[(size_t)i * NCLS + lane] = acc0 + self * g_t[(size_t)i * NCLS + lane] + b2[lane];
    if (lane < 8)
        out[(size_t)i * NCLS + c1] = acc1 + self * g_t[(size_t)i * NCLS + c1] + b2[c1];
}

// ---------------------------------------------------------------------------
// Entry point
// ---------------------------------------------------------------------------
extern "C" void kernel_launch(void* const* d_in, const int* in_sizes, int n_in,
                              void* d_out, int out_size) {
    const float* x   = (const float*)d_in[0];
    const int*   ei  = (const int*)d_in[1];
    const float* W1  = (const float*)d_in[2];
    const float* b1  = (const float*)d_in[3];
    const float* W2  = (const float*)d_in[4];
    const float* b2  = (const float*)d_in[5];
    float*       out = (float*)d_out;

    const int* src = ei;           // edge_index[0]
    const int* dst = ei + NEDGES;  // edge_index[1]

    // CSR build
    zero_cnt_kernel<<<40, 256>>>();
    count_kernel<<<(NEDGES + 255) / 256, 256>>>(dst);
    scan_kernel<<<1, 1024>>>();
    dinv_cursor_kernel<<<40, 256>>>();
    fill_kernel<<<(NEDGES + 255) / 256, 256>>>(src, dst);

    // Layer 1: propagate(x) @ W1 + b1, relu
    gather1_kernel<<<NNODES, 128>>>(x);
    {
        dim3 grid(DHID / 128, (NNODES + 127) / 128);
        sgemm1_kernel<<<grid, 256>>>(W1, b1);
    }

    // Layer 2: propagate(h @ W2) + b2
    sgemm2_kernel<<<(NNODES + 63) / 64, 256>>>(W2);
    gather2_kernel<<<(NNODES * 32 + 127) / 128, 128>>>(b2, out);
}

// round 3
// speedup vs baseline: 1.8366x; 1.8366x over previous
#include <cuda_runtime.h>
#include <cuda_bf16.h>
#include <math.h>
#include <stdint.h>

// Problem constants (fixed by the reference)
#define NNODES 10000
#define NEDGES 320000
#define DIN    512
#define DHID   2048
#define NCLS   40

// Split-bf16 extended-K GEMM1 dims
#define KTOT    1536              // [hi | hi | lo] x [hi | lo | hi]
#define GA_ROWS 10112             // 79 * 128 (padded M; pad rows stay zero)
#define BM      128
#define BN      128
#define BK      64                // 64 bf16 = 128 B per SMEM row
#define NKIT    (KTOT / BK)       // 24

// ---------------------------------------------------------------------------
// Device scratch (static globals: no runtime allocation allowed)
// ---------------------------------------------------------------------------
__device__ int   g_cnt[NNODES];
__device__ int   g_rowptr[NNODES + 1];
__device__ int   g_cursor[NNODES];
__device__ float g_dinv[NNODES];
__device__ int   g_csr_src[NEDGES];
__device__ float g_csr_coef[NEDGES];
__device__ __nv_bfloat16 g_Abf[(size_t)GA_ROWS * KTOT];  // A' split-bf16 (31 MB)
__device__ __nv_bfloat16 g_Bbf[(size_t)DHID * KTOT];     // W1^T split-bf16 (6.3 MB)
__device__ float g_h[(size_t)NNODES * DHID];             // hidden (82 MB)
__device__ float g_t[(size_t)NNODES * NCLS];             // h @ W2 (1.6 MB)

// ---------------------------------------------------------------------------
// PTX helpers (baseline sm_80+ ISA only: cp.async / ldmatrix / mma.sync)
// ---------------------------------------------------------------------------
__device__ __forceinline__ uint32_t smem_u32(const void* p) {
    uint32_t a;
    asm("{ .reg .u64 t; cvta.to.shared.u64 t, %1; cvt.u32.u64 %0, t; }"
        : "=r"(a) : "l"(p));
    return a;
}

__device__ __forceinline__ void cp_async16(uint32_t saddr, const void* gaddr) {
    asm volatile("cp.async.cg.shared.global [%0], [%1], 16;"
                 :: "r"(saddr), "l"(gaddr) : "memory");
}
__device__ __forceinline__ void cp_commit() {
    asm volatile("cp.async.commit_group;" ::: "memory");
}
template <int N>
__device__ __forceinline__ void cp_wait() {
    asm volatile("cp.async.wait_group %0;" :: "n"(N) : "memory");
}

__device__ __forceinline__ void ldsm_x4(uint32_t addr, uint32_t& r0, uint32_t& r1,
                                        uint32_t& r2, uint32_t& r3) {
    asm volatile("ldmatrix.sync.aligned.m8n8.x4.shared.b16 {%0,%1,%2,%3}, [%4];"
                 : "=r"(r0), "=r"(r1), "=r"(r2), "=r"(r3) : "r"(addr));
}

__device__ __forceinline__ void mma_bf16(float* d, const uint32_t* a, const uint32_t* b) {
    asm volatile(
        "mma.sync.aligned.m16n8k16.row.col.f32.bf16.bf16.f32 "
        "{%0,%1,%2,%3}, {%4,%5,%6,%7}, {%8,%9}, {%0,%1,%2,%3};"
        : "+f"(d[0]), "+f"(d[1]), "+f"(d[2]), "+f"(d[3])
        : "r"(a[0]), "r"(a[1]), "r"(a[2]), "r"(a[3]), "r"(b[0]), "r"(b[1]));
}

// ---------------------------------------------------------------------------
// CSR construction
// ---------------------------------------------------------------------------
__global__ void zero_cnt_kernel() {
    for (int i = blockIdx.x * blockDim.x + threadIdx.x; i < NNODES;
         i += gridDim.x * blockDim.x)
        g_cnt[i] = 0;
}

__global__ void count_kernel(const int* __restrict__ dst) {
    int e = blockIdx.x * blockDim.x + threadIdx.x;
    if (e < NEDGES) atomicAdd(&g_cnt[dst[e]], 1);
}

__global__ void scan_kernel() {
    __shared__ int sh[1024];
    __shared__ int carry;
    int tid = threadIdx.x;
    if (tid == 0) { carry = 0; g_rowptr[0] = 0; }
    __syncthreads();
    for (int base = 0; base < NNODES; base += 1024) {
        int i = base + tid;
        int v = (i < NNODES) ? g_cnt[i] : 0;
        sh[tid] = v;
        __syncthreads();
        #pragma unroll
        for (int off = 1; off < 1024; off <<= 1) {
            int t = (tid >= off) ? sh[tid - off] : 0;
            __syncthreads();
            sh[tid] += t;
            __syncthreads();
        }
        int incl = sh[tid];
        if (i < NNODES) g_rowptr[i + 1] = carry + incl;
        __syncthreads();
        if (tid == 1023) carry += sh[1023];
        __syncthreads();
    }
}

__global__ void dinv_cursor_kernel() {
    for (int i = blockIdx.x * blockDim.x + threadIdx.x; i < NNODES;
         i += gridDim.x * blockDim.x) {
        g_dinv[i]   = rsqrtf((float)g_cnt[i] + 1.0f);
        g_cursor[i] = g_rowptr[i];
    }
}

__global__ void fill_kernel(const int* __restrict__ src, const int* __restrict__ dst) {
    int e = blockIdx.x * blockDim.x + threadIdx.x;
    if (e >= NEDGES) return;
    int s = src[e], d = dst[e];
    int p = atomicAdd(&g_cursor[d], 1);
    g_csr_src[p]  = s;
    g_csr_coef[p] = g_dinv[s] * g_dinv[d];
}

// ---------------------------------------------------------------------------
// W1 prep: g_Bbf[n][0:512)=hi, [512:1024)=lo, [1024:1536)=hi  (W1 transposed)
// ---------------------------------------------------------------------------
__global__ void w1prep_kernel(const float* __restrict__ W1) {
    int n = blockIdx.x;
    __nv_bfloat16* row = &g_Bbf[(size_t)n * KTOT];
    for (int k = threadIdx.x; k < DIN; k += blockDim.x) {
        float w = W1[(size_t)k * DHID + n];
        __nv_bfloat16 hi = __float2bfloat16(w);
        __nv_bfloat16 lo = __float2bfloat16(w - __bfloat162float(hi));
        row[k]        = hi;
        row[512 + k]  = lo;
        row[1024 + k] = hi;
    }
}

// ---------------------------------------------------------------------------
// Layer-1 propagate + split-bf16 pack:
//   acc[i] = sum coef*x[j] + dinv^2*x[i];  A'[i] = [hi | hi | lo]
// ---------------------------------------------------------------------------
__global__ void gather1_kernel(const float* __restrict__ x) {
    int i = blockIdx.x;
    int f4 = threadIdx.x;
    float di = g_dinv[i];
    float self = di * di;
    float4 xv = ((const float4*)&x[(size_t)i * DIN])[f4];
    float4 acc;
    acc.x = self * xv.x; acc.y = self * xv.y;
    acc.z = self * xv.z; acc.w = self * xv.w;
    int beg = g_rowptr[i], end = g_rowptr[i + 1];
    for (int j = beg; j < end; j++) {
        int s = g_csr_src[j];
        float c = g_csr_coef[j];
        float4 v = ((const float4*)&x[(size_t)s * DIN])[f4];
        acc.x += c * v.x; acc.y += c * v.y;
        acc.z += c * v.z; acc.w += c * v.w;
    }
    float a[4] = {acc.x, acc.y, acc.z, acc.w};
    union { __nv_bfloat16 h[4]; uint2 u; } hp, lp;
    #pragma unroll
    for (int t = 0; t < 4; t++) {
        hp.h[t] = __float2bfloat16(a[t]);
        lp.h[t] = __float2bfloat16(a[t] - __bfloat162float(hp.h[t]));
    }
    int k = f4 * 4;
    __nv_bfloat16* row = &g_Abf[(size_t)i * KTOT];
    *(uint2*)&row[k]        = hp.u;
    *(uint2*)&row[512 + k]  = hp.u;
    *(uint2*)&row[1024 + k] = lp.u;
}

// ---------------------------------------------------------------------------
// GEMM1 (mma.sync bf16): g_h = relu(A'[10112x1536] @ B'[2048x1536]^T + b1)
// 128x128x64 tile, cp.async double buffer, 8 warps each 32(m)x64(n).
// SMEM row = 64 bf16 = 128 B, XOR-swizzled in 16B chunks (conflict-free LDSM).
// ---------------------------------------------------------------------------
#define STAGE_BYTES (BM * BK * 2 + BN * BK * 2)   // 32768
#define GEMM1_SMEM  (2 * STAGE_BYTES)             // 65536

__global__ __launch_bounds__(256, 2)
void gemm1_mma_kernel(const float* __restrict__ bias) {
    extern __shared__ char dsm[];
    const uint32_t sbase = smem_u32(dsm);
    const int tid  = threadIdx.x;
    const int wid  = tid >> 5;
    const int lane = tid & 31;
    const int warp_m = wid & 3;       // 4 warps over M=128 (32 rows each)
    const int warp_n = wid >> 2;      // 2 warps over N=128 (64 cols each)
    const int block_n = blockIdx.x * BN;
    const int block_m = blockIdx.y * BM;

    uint32_t sA[2] = { sbase, sbase + STAGE_BYTES };
    uint32_t sB[2] = { sbase + (uint32_t)(BM * BK * 2),
                       sbase + STAGE_BYTES + (uint32_t)(BM * BK * 2) };

    const __nv_bfloat16* gA = g_Abf;
    const __nv_bfloat16* gB = g_Bbf;

    // Per-thread load slots: 1024 16B-chunks per operand per stage, 4 each.
    int ld_row = 0, ld_c = 0;  // computed per slot in the loop
    (void)ld_row; (void)ld_c;

    auto load_stage = [&](int kt, int s) {
        const int k0 = kt * BK;
        #pragma unroll
        for (int i = 0; i < 4; i++) {
            int t = tid + i * 256;
            int row = t >> 3, c = t & 7;
            uint32_t sw = (uint32_t)(row << 7) + (uint32_t)(((c ^ (row & 7)) << 4));
            cp_async16(sA[s] + sw, &gA[(size_t)(block_m + row) * KTOT + k0 + c * 8]);
        }
        #pragma unroll
        for (int i = 0; i < 4; i++) {
            int t = tid + i * 256;
            int row = t >> 3, c = t & 7;
            uint32_t sw = (uint32_t)(row << 7) + (uint32_t)(((c ^ (row & 7)) << 4));
            cp_async16(sB[s] + sw, &gB[(size_t)(block_n + row) * KTOT + k0 + c * 8]);
        }
        cp_commit();
    };

    // ldmatrix lane geometry
    const int grp  = lane >> 3;      // which 8x8 matrix this lane addresses
    const int lrow = lane & 7;
    // A (x4): mats = {m0-7 kc0, m8-15 kc0, m0-7 kc1, m8-15 kc1}
    const int arow0 = warp_m * 32 + ((grp & 1) << 3) + lrow;   // mt=0
    const int arow1 = arow0 + 16;                              // mt=1
    const int akc_half = grp >> 1;
    // B (x4): mats = {n0-7 kc0, n0-7 kc1, n8-15 kc0, n8-15 kc1}
    const int brow_base = warp_n * 64 + ((grp >> 1) << 3) + lrow;
    const int bkc_half = grp & 1;

    float acc[2][8][4];
    #pragma unroll
    for (int i = 0; i < 2; i++)
        #pragma unroll
        for (int j = 0; j < 8; j++)
            #pragma unroll
            for (int q = 0; q < 4; q++) acc[i][j][q] = 0.0f;

    load_stage(0, 0);
    load_stage(1, 1);
    cp_wait<1>();
    __syncthreads();

    for (int kt = 0; kt < NKIT; kt++) {
        const int cur = kt & 1;
        // compute on stage cur: 4 ksteps of K=16
        #pragma unroll
        for (int ks = 0; ks < 4; ks++) {
            uint32_t a0[4], a1[4];
            const int kca = 2 * ks + akc_half;
            ldsm_x4(sA[cur] + (uint32_t)(arow0 << 7) + (uint32_t)(((kca ^ (arow0 & 7)) << 4)),
                    a0[0], a0[1], a0[2], a0[3]);
            ldsm_x4(sA[cur] + (uint32_t)(arow1 << 7) + (uint32_t)(((kca ^ (arow1 & 7)) << 4)),
                    a1[0], a1[1], a1[2], a1[3]);
            const int kcb = 2 * ks + bkc_half;
            uint32_t b[4][4];
            #pragma unroll
            for (int p = 0; p < 4; p++) {
                const int brow = brow_base + p * 16;
                ldsm_x4(sB[cur] + (uint32_t)(brow << 7) + (uint32_t)(((kcb ^ (brow & 7)) << 4)),
                        b[p][0], b[p][1], b[p][2], b[p][3]);
            }
            #pragma unroll
            for (int p = 0; p < 4; p++) {
                mma_bf16(acc[0][2 * p + 0], a0, &b[p][0]);
                mma_bf16(acc[0][2 * p + 1], a0, &b[p][2]);
                mma_bf16(acc[1][2 * p + 0], a1, &b[p][0]);
                mma_bf16(acc[1][2 * p + 1], a1, &b[p][2]);
            }
        }
        __syncthreads();             // everyone done reading stage cur
        if (kt + 2 < NKIT) {
            load_stage(kt + 2, cur); // reuse stage cur for chunk kt+2
            cp_wait<1>();            // chunk kt+1 complete
        } else {
            cp_wait<0>();
        }
        __syncthreads();
    }

    // Epilogue: acc -> g_h with +bias, relu
    const int grpID = lane >> 2;
    const int tg    = lane & 3;
    #pragma unroll
    for (int mt = 0; mt < 2; mt++) {
        const int row0 = block_m + warp_m * 32 + mt * 16 + grpID;
        const int row1 = row0 + 8;
        #pragma unroll
        for (int nt = 0; nt < 8; nt++) {
            const int col = block_n + warp_n * 64 + nt * 8 + tg * 2;
            const float bi0 = bias[col], bi1 = bias[col + 1];
            if (row0 < NNODES) {
                float2 v;
                v.x = fmaxf(acc[mt][nt][0] + bi0, 0.f);
                v.y = fmaxf(acc[mt][nt][1] + bi1, 0.f);
                *(float2*)&g_h[(size_t)row0 * DHID + col] = v;
            }
            if (row1 < NNODES) {
                float2 v;
                v.x = fmaxf(acc[mt][nt][2] + bi0, 0.f);
                v.y = fmaxf(acc[mt][nt][3] + bi1, 0.f);
                *(float2*)&g_h[(size_t)row1 * DHID + col] = v;
            }
        }
    }
}

// ---------------------------------------------------------------------------
// SGEMM2: g_t = g_h[10000x2048] @ W2[2048x40]
// ---------------------------------------------------------------------------
__global__ __launch_bounds__(256)
void sgemm2_kernel(const float* __restrict__ B /*W2*/) {
    __shared__ float As[32][65];
    __shared__ float Bs[32][40];
    const float* A = g_h;
    float*       C = g_t;

    int block_m = blockIdx.x * 64;
    int tid = threadIdx.x;
    int tr = tid >> 3;
    int tc = tid & 7;

    float acc[2][5];
    #pragma unroll
    for (int i = 0; i < 2; i++)
        #pragma unroll
        for (int j = 0; j < 5; j++) acc[i][j] = 0.0f;

    for (int k0 = 0; k0 < DHID; k0 += 32) {
        #pragma unroll
        for (int r = 0; r < 2; r++) {
            int q = tid + 256 * r;
            int row = q >> 3;
            int col = (q & 7) << 2;
            float4 av = make_float4(0.f, 0.f, 0.f, 0.f);
            int gm = block_m + row;
            if (gm < NNODES) av = *(const float4*)&A[(size_t)gm * DHID + k0 + col];
            As[col + 0][row] = av.x;
            As[col + 1][row] = av.y;
            As[col + 2][row] = av.z;
            As[col + 3][row] = av.w;
        }
        #pragma unroll
        for (int r = 0; r < 5; r++) {
            int q = tid + 256 * r;
            int row = q / 40;
            int col = q % 40;
            Bs[row][col] = B[(size_t)(k0 + row) * NCLS + col];
        }
        __syncthreads();
        #pragma unroll
        for (int k = 0; k < 32; k++) {
            float a0 = As[k][tr * 2 + 0];
            float a1 = As[k][tr * 2 + 1];
            float b[5];
            #pragma unroll
            for (int j = 0; j < 5; j++) b[j] = Bs[k][tc * 5 + j];
            #pragma unroll
            for (int j = 0; j < 5; j++) {
                acc[0][j] += a0 * b[j];
                acc[1][j] += a1 * b[j];
            }
        }
        __syncthreads();
    }

    #pragma unroll
    for (int i = 0; i < 2; i++) {
        int gm = block_m + tr * 2 + i;
        if (gm >= NNODES) continue;
        #pragma unroll
        for (int j = 0; j < 5; j++)
            C[(size_t)gm * NCLS + tc * 5 + j] = acc[i][j];
    }
}

// ---------------------------------------------------------------------------
// Layer-2 propagate + bias
// ---------------------------------------------------------------------------
__global__ void gather2_kernel(const float* __restrict__ b2, float* __restrict__ out) {
    int gw = (blockIdx.x * blockDim.x + threadIdx.x) >> 5;
    int lane = threadIdx.x & 31;
    if (gw >= NNODES) return;
    int i = gw;
    float di = g_dinv[i];
    float self = di * di;
    int c1 = lane + 32;
    float acc0 = 0.f, acc1 = 0.f;
    int beg = g_rowptr[i], end = g_rowptr[i + 1];
    for (int j = beg; j < end; j++) {
        int s = g_csr_src[j];
        float c = g_csr_coef[j];
        acc0 += c * g_t[(size_t)s * NCLS + lane];
        if (lane < 8) acc1 += c * g_t[(size_t)s * NCLS + c1];
    }
    out[(size_t)i * NCLS + lane] = acc0 + self * g_t[(size_t)i * NCLS + lane] + b2[lane];
    if (lane < 8)
        out[(size_t)i * NCLS + c1] = acc1 + self * g_t[(size_t)i * NCLS + c1] + b2[c1];
}

// ---------------------------------------------------------------------------
// Entry point
// ---------------------------------------------------------------------------
extern "C" void kernel_launch(void* const* d_in, const int* in_sizes, int n_in,
                              void* d_out, int out_size) {
    const float* x   = (const float*)d_in[0];
    const int*   ei  = (const int*)d_in[1];
    const float* W1  = (const float*)d_in[2];
    const float* b1  = (const float*)d_in[3];
    const float* W2  = (const float*)d_in[4];
    const float* b2  = (const float*)d_in[5];
    float*       out = (float*)d_out;

    const int* src = ei;
    const int* dst = ei + NEDGES;

    cudaFuncSetAttribute(gemm1_mma_kernel,
                         cudaFuncAttributeMaxDynamicSharedMemorySize, GEMM1_SMEM);

    // CSR build
    zero_cnt_kernel<<<40, 256>>>();
    count_kernel<<<(NEDGES + 255) / 256, 256>>>(dst);
    scan_kernel<<<1, 1024>>>();
    dinv_cursor_kernel<<<40, 256>>>();
    fill_kernel<<<(NEDGES + 255) / 256, 256>>>(src, dst);

    // W1 split prep
    w1prep_kernel<<<DHID, 128>>>(W1);

    // Layer 1: propagate(x) packed to split-bf16, then mma.sync GEMM +b1+relu
    gather1_kernel<<<NNODES, 128>>>(x);
    {
        dim3 grid(DHID / BN, GA_ROWS / BM);   // (16, 79)
        gemm1_mma_kernel<<<grid, 256, GEMM1_SMEM>>>(b1);
    }

    // Layer 2
    sgemm2_kernel<<<(NNODES + 63) / 64, 256>>>(W2);
    gather2_kernel<<<(NNODES * 32 + 127) / 128, 128>>>(b2, out);
}

// round 4
// speedup vs baseline: 2.6631x; 1.4500x over previous
#include <cuda_runtime.h>
#include <cuda_bf16.h>
#include <math.h>
#include <stdint.h>

// Problem constants (fixed by the reference)
#define NNODES 10000
#define NEDGES 320000
#define DIN    512
#define DHID   2048
#define NCLS   40

#define GA_ROWS 10112             // 79 * 128 (padded M; pad rows stay zero)

// GEMM1: A'[M x 1024]=[hi|lo], B'(W1^T)[2048 x 1536]=[hi|lo|hi], 24 K-chunks
#define KA1     1024
#define KB1     1536
#define BM      128
#define BN      128
#define BK      64                // 64 bf16 = 128 B per SMEM row
#define NKIT    24

// GEMM2: A2'(h')[M x 4096]=[hi|lo], B2'(W2^T)[48 x 4096]=[hi|lo], 96 K-chunks
#define KA2     4096
#define BM2     64
#define BN2     48                // padded from 40
#define NKIT2   96

// ---------------------------------------------------------------------------
// Device scratch (static globals: no runtime allocation allowed)
// ---------------------------------------------------------------------------
__device__ int   g_cnt[NNODES];
__device__ int   g_rowptr[NNODES + 1];
__device__ int   g_cursor[NNODES];
__device__ float g_dinv[NNODES];
__device__ int   g_csr_src[NEDGES];
__device__ float g_csr_coef[NEDGES];
__device__ __nv_bfloat16 g_Abf[(size_t)GA_ROWS * KA1];   // 20.7 MB
__device__ __nv_bfloat16 g_Bbf[(size_t)DHID * KB1];      // 6.3 MB
__device__ __nv_bfloat16 g_hbf[(size_t)GA_ROWS * KA2];   // 82.8 MB
__device__ __nv_bfloat16 g_W2bf[(size_t)BN2 * KA2];      // 393 KB
__device__ float g_t[(size_t)NNODES * NCLS];             // 1.6 MB

// ---------------------------------------------------------------------------
// PTX helpers (baseline sm_80+ ISA: cp.async / ldmatrix / mma.sync)
// ---------------------------------------------------------------------------
__device__ __forceinline__ uint32_t smem_u32(const void* p) {
    uint32_t a;
    asm("{ .reg .u64 t; cvta.to.shared.u64 t, %1; cvt.u32.u64 %0, t; }"
        : "=r"(a) : "l"(p));
    return a;
}
__device__ __forceinline__ void cp_async16(uint32_t saddr, const void* gaddr) {
    asm volatile("cp.async.cg.shared.global [%0], [%1], 16;"
                 :: "r"(saddr), "l"(gaddr) : "memory");
}
__device__ __forceinline__ void cp_commit() {
    asm volatile("cp.async.commit_group;" ::: "memory");
}
template <int N>
__device__ __forceinline__ void cp_wait() {
    asm volatile("cp.async.wait_group %0;" :: "n"(N) : "memory");
}
__device__ __forceinline__ void ldsm_x4(uint32_t addr, uint32_t& r0, uint32_t& r1,
                                        uint32_t& r2, uint32_t& r3) {
    asm volatile("ldmatrix.sync.aligned.m8n8.x4.shared.b16 {%0,%1,%2,%3}, [%4];"
                 : "=r"(r0), "=r"(r1), "=r"(r2), "=r"(r3) : "r"(addr));
}
__device__ __forceinline__ void mma_bf16(float* d, const uint32_t* a, const uint32_t* b) {
    asm volatile(
        "mma.sync.aligned.m16n8k16.row.col.f32.bf16.bf16.f32 "
        "{%0,%1,%2,%3}, {%4,%5,%6,%7}, {%8,%9}, {%0,%1,%2,%3};"
        : "+f"(d[0]), "+f"(d[1]), "+f"(d[2]), "+f"(d[3])
        : "r"(a[0]), "r"(a[1]), "r"(a[2]), "r"(a[3]), "r"(b[0]), "r"(b[1]));
}

union BfPair { __nv_bfloat16 h[2]; uint32_t u; };

// ---------------------------------------------------------------------------
// CSR construction
// ---------------------------------------------------------------------------
__global__ void zero_cnt_kernel() {
    for (int i = blockIdx.x * blockDim.x + threadIdx.x; i < NNODES;
         i += gridDim.x * blockDim.x)
        g_cnt[i] = 0;
}
__global__ void count_kernel(const int* __restrict__ dst) {
    int e = blockIdx.x * blockDim.x + threadIdx.x;
    if (e < NEDGES) atomicAdd(&g_cnt[dst[e]], 1);
}
__global__ void scan_kernel() {
    __shared__ int sh[1024];
    __shared__ int carry;
    int tid = threadIdx.x;
    if (tid == 0) { carry = 0; g_rowptr[0] = 0; }
    __syncthreads();
    for (int base = 0; base < NNODES; base += 1024) {
        int i = base + tid;
        int v = (i < NNODES) ? g_cnt[i] : 0;
        sh[tid] = v;
        __syncthreads();
        #pragma unroll
        for (int off = 1; off < 1024; off <<= 1) {
            int t = (tid >= off) ? sh[tid - off] : 0;
            __syncthreads();
            sh[tid] += t;
            __syncthreads();
        }
        int incl = sh[tid];
        if (i < NNODES) g_rowptr[i + 1] = carry + incl;
        __syncthreads();
        if (tid == 1023) carry += sh[1023];
        __syncthreads();
    }
}
__global__ void dinv_cursor_kernel() {
    for (int i = blockIdx.x * blockDim.x + threadIdx.x; i < NNODES;
         i += gridDim.x * blockDim.x) {
        g_dinv[i]   = rsqrtf((float)g_cnt[i] + 1.0f);
        g_cursor[i] = g_rowptr[i];
    }
}
__global__ void fill_kernel(const int* __restrict__ src, const int* __restrict__ dst) {
    int e = blockIdx.x * blockDim.x + threadIdx.x;
    if (e >= NEDGES) return;
    int s = src[e], d = dst[e];
    int p = atomicAdd(&g_cursor[d], 1);
    g_csr_src[p]  = s;
    g_csr_coef[p] = g_dinv[s] * g_dinv[d];
}

// ---------------------------------------------------------------------------
// W1 prep (tiled transpose): g_Bbf[n] = [hi(512) | lo(512) | hi(512)]
// grid (DIN/32, DHID/32), block (32,8)
// ---------------------------------------------------------------------------
__global__ void w1prep_kernel(const float* __restrict__ W1) {
    __shared__ float tile[32][33];
    int k0 = blockIdx.x * 32, n0 = blockIdx.y * 32;
    int tx = threadIdx.x, ty = threadIdx.y;
    #pragma unroll
    for (int j = 0; j < 4; j++)
        tile[ty + 8 * j][tx] = W1[(size_t)(k0 + ty + 8 * j) * DHID + n0 + tx];
    __syncthreads();
    #pragma unroll
    for (int j = 0; j < 4; j++) {
        int n = n0 + ty + 8 * j;
        int k = k0 + tx;
        float w = tile[tx][ty + 8 * j];
        __nv_bfloat16 hi = __float2bfloat16(w);
        __nv_bfloat16 lo = __float2bfloat16(w - __bfloat162float(hi));
        __nv_bfloat16* row = &g_Bbf[(size_t)n * KB1];
        row[k]        = hi;
        row[512 + k]  = lo;
        row[1024 + k] = hi;
    }
}

// ---------------------------------------------------------------------------
// W2 prep: g_W2bf[n] = [hi(2048) | lo(2048)], rows 40..47 zero
// ---------------------------------------------------------------------------
__global__ void w2prep_kernel(const float* __restrict__ W2) {
    int n = blockIdx.x;                 // 0..47
    __nv_bfloat16* row = &g_W2bf[(size_t)n * KA2];
    for (int k = threadIdx.x; k < DHID; k += blockDim.x) {
        float w = (n < NCLS) ? W2[(size_t)k * NCLS + n] : 0.0f;
        __nv_bfloat16 hi = __float2bfloat16(w);
        __nv_bfloat16 lo = __float2bfloat16(w - __bfloat162float(hi));
        row[k]        = hi;
        row[2048 + k] = lo;
    }
}

// ---------------------------------------------------------------------------
// Layer-1 propagate + split pack: A'[i] = [hi | lo]
// ---------------------------------------------------------------------------
__global__ void gather1_kernel(const float* __restrict__ x) {
    int i = blockIdx.x;
    int f4 = threadIdx.x;
    float di = g_dinv[i];
    float self = di * di;
    float4 xv = ((const float4*)&x[(size_t)i * DIN])[f4];
    float4 acc;
    acc.x = self * xv.x; acc.y = self * xv.y;
    acc.z = self * xv.z; acc.w = self * xv.w;
    int beg = g_rowptr[i], end = g_rowptr[i + 1];
    for (int j = beg; j < end; j++) {
        int s = g_csr_src[j];
        float c = g_csr_coef[j];
        float4 v = ((const float4*)&x[(size_t)s * DIN])[f4];
        acc.x += c * v.x; acc.y += c * v.y;
        acc.z += c * v.z; acc.w += c * v.w;
    }
    float a[4] = {acc.x, acc.y, acc.z, acc.w};
    union { __nv_bfloat16 h[4]; uint2 u; } hp, lp;
    #pragma unroll
    for (int t = 0; t < 4; t++) {
        hp.h[t] = __float2bfloat16(a[t]);
        lp.h[t] = __float2bfloat16(a[t] - __bfloat162float(hp.h[t]));
    }
    int k = f4 * 4;
    __nv_bfloat16* row = &g_Abf[(size_t)i * KA1];
    *(uint2*)&row[k]       = hp.u;
    *(uint2*)&row[512 + k] = lp.u;
}

// ---------------------------------------------------------------------------
// GEMM1 (mma.sync bf16): h' = relu(A' @ B'^T + b1) stored split-bf16 [hi|lo]
// 128x128x64 tile, cp.async double buffer, 8 warps each 32(m)x64(n).
// K-chunk kt: a_chunk = kt<8 ? kt : kt-8 ; b_chunk = kt.
// ---------------------------------------------------------------------------
#define STAGE_BYTES (BM * BK * 2 + BN * BK * 2)   // 32768
#define GEMM1_SMEM  (2 * STAGE_BYTES)             // 65536

__global__ __launch_bounds__(256, 2)
void gemm1_mma_kernel(const float* __restrict__ bias) {
    extern __shared__ char dsm[];
    const uint32_t sbase = smem_u32(dsm);
    const int tid  = threadIdx.x;
    const int wid  = tid >> 5;
    const int lane = tid & 31;
    const int warp_m = wid & 3;
    const int warp_n = wid >> 2;
    const int block_n = blockIdx.x * BN;
    const int block_m = blockIdx.y * BM;

    uint32_t sA[2] = { sbase, sbase + STAGE_BYTES };
    uint32_t sB[2] = { sbase + (uint32_t)(BM * BK * 2),
                       sbase + STAGE_BYTES + (uint32_t)(BM * BK * 2) };

    auto load_stage = [&](int kt, int s) {
        const int ka = ((kt < 8) ? kt : kt - 8) * BK;
        const int kb = kt * BK;
        #pragma unroll
        for (int i = 0; i < 4; i++) {
            int t = tid + i * 256;
            int row = t >> 3, c = t & 7;
            uint32_t sw = (uint32_t)(row << 7) + (uint32_t)(((c ^ (row & 7)) << 4));
            cp_async16(sA[s] + sw, &g_Abf[(size_t)(block_m + row) * KA1 + ka + c * 8]);
        }
        #pragma unroll
        for (int i = 0; i < 4; i++) {
            int t = tid + i * 256;
            int row = t >> 3, c = t & 7;
            uint32_t sw = (uint32_t)(row << 7) + (uint32_t)(((c ^ (row & 7)) << 4));
            cp_async16(sB[s] + sw, &g_Bbf[(size_t)(block_n + row) * KB1 + kb + c * 8]);
        }
        cp_commit();
    };

    const int grp  = lane >> 3;
    const int lrow = lane & 7;
    const int arow0 = warp_m * 32 + ((grp & 1) << 3) + lrow;
    const int arow1 = arow0 + 16;
    const int akc_half = grp >> 1;
    const int brow_base = warp_n * 64 + ((grp >> 1) << 3) + lrow;
    const int bkc_half = grp & 1;

    float acc[2][8][4];
    #pragma unroll
    for (int i = 0; i < 2; i++)
        #pragma unroll
        for (int j = 0; j < 8; j++)
            #pragma unroll
            for (int q = 0; q < 4; q++) acc[i][j][q] = 0.0f;

    load_stage(0, 0);
    load_stage(1, 1);
    cp_wait<1>();
    __syncthreads();

    for (int kt = 0; kt < NKIT; kt++) {
        const int cur = kt & 1;
        #pragma unroll
        for (int ks = 0; ks < 4; ks++) {
            uint32_t a0[4], a1[4];
            const int kca = 2 * ks + akc_half;
            ldsm_x4(sA[cur] + (uint32_t)(arow0 << 7) + (uint32_t)(((kca ^ (arow0 & 7)) << 4)),
                    a0[0], a0[1], a0[2], a0[3]);
            ldsm_x4(sA[cur] + (uint32_t)(arow1 << 7) + (uint32_t)(((kca ^ (arow1 & 7)) << 4)),
                    a1[0], a1[1], a1[2], a1[3]);
            const int kcb = 2 * ks + bkc_half;
            uint32_t b[4][4];
            #pragma unroll
            for (int p = 0; p < 4; p++) {
                const int brow = brow_base + p * 16;
                ldsm_x4(sB[cur] + (uint32_t)(brow << 7) + (uint32_t)(((kcb ^ (brow & 7)) << 4)),
                        b[p][0], b[p][1], b[p][2], b[p][3]);
            }
            #pragma unroll
            for (int p = 0; p < 4; p++) {
                mma_bf16(acc[0][2 * p + 0], a0, &b[p][0]);
                mma_bf16(acc[0][2 * p + 1], a0, &b[p][2]);
                mma_bf16(acc[1][2 * p + 0], a1, &b[p][0]);
                mma_bf16(acc[1][2 * p + 1], a1, &b[p][2]);
            }
        }
        __syncthreads();
        if (kt + 2 < NKIT) {
            load_stage(kt + 2, cur);
            cp_wait<1>();
        } else {
            cp_wait<0>();
        }
        __syncthreads();
    }

    // Epilogue: relu(acc+bias) -> split bf16 [hi | lo] into g_hbf
    const int grpID = lane >> 2;
    const int tg    = lane & 3;
    #pragma unroll
    for (int mt = 0; mt < 2; mt++) {
        const int row0 = block_m + warp_m * 32 + mt * 16 + grpID;
        const int row1 = row0 + 8;
        #pragma unroll
        for (int nt = 0; nt < 8; nt++) {
            const int col = block_n + warp_n * 64 + nt * 8 + tg * 2;
            const float bi0 = bias[col], bi1 = bias[col + 1];
            {
                float v0 = fmaxf(acc[mt][nt][0] + bi0, 0.f);
                float v1 = fmaxf(acc[mt][nt][1] + bi1, 0.f);
                BfPair hp, lp;
                hp.h[0] = __float2bfloat16(v0);
                hp.h[1] = __float2bfloat16(v1);
                lp.h[0] = __float2bfloat16(v0 - __bfloat162float(hp.h[0]));
                lp.h[1] = __float2bfloat16(v1 - __bfloat162float(hp.h[1]));
                size_t base = (size_t)row0 * KA2;
                *(uint32_t*)&g_hbf[base + col]        = hp.u;
                *(uint32_t*)&g_hbf[base + 2048 + col] = lp.u;
            }
            {
                float v0 = fmaxf(acc[mt][nt][2] + bi0, 0.f);
                float v1 = fmaxf(acc[mt][nt][3] + bi1, 0.f);
                BfPair hp, lp;
                hp.h[0] = __float2bfloat16(v0);
                hp.h[1] = __float2bfloat16(v1);
                lp.h[0] = __float2bfloat16(v0 - __bfloat162float(hp.h[0]));
                lp.h[1] = __float2bfloat16(v1 - __bfloat162float(hp.h[1]));
                size_t base = (size_t)row1 * KA2;
                *(uint32_t*)&g_hbf[base + col]        = hp.u;
                *(uint32_t*)&g_hbf[base + 2048 + col] = lp.u;
            }
        }
    }
}

// ---------------------------------------------------------------------------
// GEMM2 (mma.sync bf16): g_t = h' @ W2'^T  (3-product split over 96 K-chunks)
// 64x48x64 tile, 128 threads (4 warps over M), double-buffered cp.async.
// ---------------------------------------------------------------------------
#define STAGE2_BYTES (BM2 * BK * 2 + BN2 * BK * 2)   // 14336
#define GEMM2_SMEM   (2 * STAGE2_BYTES)              // 28672

__global__ __launch_bounds__(128, 4)
void gemm2_mma_kernel() {
    extern __shared__ char dsm[];
    const uint32_t sbase = smem_u32(dsm);
    const int tid  = threadIdx.x;
    const int wid  = tid >> 5;        // warp_m 0..3
    const int lane = tid & 31;
    const int block_m = blockIdx.x * BM2;

    uint32_t sA[2] = { sbase, sbase + STAGE2_BYTES };
    uint32_t sB[2] = { sbase + (uint32_t)(BM2 * BK * 2),
                       sbase + STAGE2_BYTES + (uint32_t)(BM2 * BK * 2) };

    auto load_stage = [&](int kt, int s) {
        const int ka = ((kt < 32) ? kt : kt - 32) * BK;
        const int kb = ((kt < 64) ? kt : kt - 64) * BK;
        #pragma unroll
        for (int i = 0; i < 4; i++) {
            int t = tid + i * 128;               // 0..511
            int row = t >> 3, c = t & 7;
            uint32_t sw = (uint32_t)(row << 7) + (uint32_t)(((c ^ (row & 7)) << 4));
            cp_async16(sA[s] + sw, &g_hbf[(size_t)(block_m + row) * KA2 + ka + c * 8]);
        }
        #pragma unroll
        for (int i = 0; i < 3; i++) {
            int t = tid + i * 128;               // 0..383
            int row = t >> 3, c = t & 7;
            uint32_t sw = (uint32_t)(row << 7) + (uint32_t)(((c ^ (row & 7)) << 4));
            cp_async16(sB[s] + sw, &g_W2bf[(size_t)row * KA2 + kb + c * 8]);
        }
        cp_commit();
    };

    const int grp  = lane >> 3;
    const int lrow = lane & 7;
    const int arow = wid * 16 + ((grp & 1) << 3) + lrow;
    const int akc_half = grp >> 1;
    const int brow_base = ((grp >> 1) << 3) + lrow;
    const int bkc_half = grp & 1;

    float acc[6][4];
    #pragma unroll
    for (int j = 0; j < 6; j++)
        #pragma unroll
        for (int q = 0; q < 4; q++) acc[j][q] = 0.0f;

    load_stage(0, 0);
    load_stage(1, 1);
    cp_wait<1>();
    __syncthreads();

    for (int kt = 0; kt < NKIT2; kt++) {
        const int cur = kt & 1;
        #pragma unroll
        for (int ks = 0; ks < 4; ks++) {
            uint32_t a[4];
            const int kca = 2 * ks + akc_half;
            ldsm_x4(sA[cur] + (uint32_t)(arow << 7) + (uint32_t)(((kca ^ (arow & 7)) << 4)),
                    a[0], a[1], a[2], a[3]);
            const int kcb = 2 * ks + bkc_half;
            uint32_t b[3][4];
            #pragma unroll
            for (int p = 0; p < 3; p++) {
                const int brow = brow_base + p * 16;
                ldsm_x4(sB[cur] + (uint32_t)(brow << 7) + (uint32_t)(((kcb ^ (brow & 7)) << 4)),
                        b[p][0], b[p][1], b[p][2], b[p][3]);
            }
            #pragma unroll
            for (int p = 0; p < 3; p++) {
                mma_bf16(acc[2 * p + 0], a, &b[p][0]);
                mma_bf16(acc[2 * p + 1], a, &b[p][2]);
            }
        }
        __syncthreads();
        if (kt + 2 < NKIT2) {
            load_stage(kt + 2, cur);
            cp_wait<1>();
        } else {
            cp_wait<0>();
        }
        __syncthreads();
    }

    // Epilogue: write 40 real columns
    const int grpID = lane >> 2;
    const int tg    = lane & 3;
    const int row0 = block_m + wid * 16 + grpID;
    const int row1 = row0 + 8;
    #pragma unroll
    for (int nt = 0; nt < 5; nt++) {
        const int col = nt * 8 + tg * 2;
        if (row0 < NNODES)
            *(float2*)&g_t[(size_t)row0 * NCLS + col] = make_float2(acc[nt][0], acc[nt][1]);
        if (row1 < NNODES)
            *(float2*)&g_t[(size_t)row1 * NCLS + col] = make_float2(acc[nt][2], acc[nt][3]);
    }
}

// ---------------------------------------------------------------------------
// Layer-2 propagate + bias
// ---------------------------------------------------------------------------
__global__ void gather2_kernel(const float* __restrict__ b2, float* __restrict__ out) {
    int gw = (blockIdx.x * blockDim.x + threadIdx.x) >> 5;
    int lane = threadIdx.x & 31;
    if (gw >= NNODES) return;
    int i = gw;
    float di = g_dinv[i];
    float self = di * di;
    int c1 = lane + 32;
    float acc0 = 0.f, acc1 = 0.f;
    int beg = g_rowptr[i], end = g_rowptr[i + 1];
    for (int j = beg; j < end; j++) {
        int s = g_csr_src[j];
        float c = g_csr_coef[j];
        acc0 += c * g_t[(size_t)s * NCLS + lane];
        if (lane < 8) acc1 += c * g_t[(size_t)s * NCLS + c1];
    }
    out[(size_t)i * NCLS + lane] = acc0 + self * g_t[(size_t)i * NCLS + lane] + b2[lane];
    if (lane < 8)
        out[(size_t)i * NCLS + c1] = acc1 + self * g_t[(size_t)i * NCLS + c1] + b2[c1];
}

// ---------------------------------------------------------------------------
// Entry point
// ---------------------------------------------------------------------------
extern "C" void kernel_launch(void* const* d_in, const int* in_sizes, int n_in,
                              void* d_out, int out_size) {
    const float* x   = (const float*)d_in[0];
    const int*   ei  = (const int*)d_in[1];
    const float* W1  = (const float*)d_in[2];
    const float* b1  = (const float*)d_in[3];
    const float* W2  = (const float*)d_in[4];
    const float* b2  = (const float*)d_in[5];
    float*       out = (float*)d_out;

    const int* src = ei;
    const int* dst = ei + NEDGES;

    cudaFuncSetAttribute(gemm1_mma_kernel,
                         cudaFuncAttributeMaxDynamicSharedMemorySize, GEMM1_SMEM);

    // CSR build
    zero_cnt_kernel<<<40, 256>>>();
    count_kernel<<<(NEDGES + 255) / 256, 256>>>(dst);
    scan_kernel<<<1, 1024>>>();
    dinv_cursor_kernel<<<40, 256>>>();
    fill_kernel<<<(NEDGES + 255) / 256, 256>>>(src, dst);

    // Weight preps
    {
        dim3 grid(DIN / 32, DHID / 32), block(32, 8);
        w1prep_kernel<<<grid, block>>>(W1);
    }
    w2prep_kernel<<<BN2, 256>>>(W2);

    // Layer 1
    gather1_kernel<<<NNODES, 128>>>(x);
    {
        dim3 grid(DHID / BN, GA_ROWS / BM);   // (16, 79)
        gemm1_mma_kernel<<<grid, 256, GEMM1_SMEM>>>(b1);
    }

    // Layer 2
    gemm2_mma_kernel<<<GA_ROWS / BM2, 128, GEMM2_SMEM>>>();
    gather2_kernel<<<(NNODES * 32 + 127) / 128, 128>>>(b2, out);
}